// round 8
// baseline (speedup 1.0000x reference)
#include <cuda_runtime.h>

#define DD 64
#define MAXN 50048
#define MAXE 800000
#define CAP 64

// Scratch (__device__ globals; no allocations allowed).
__device__ float4 g_tl[MAXN * 16];   // A @ Wl^T   (reused by both layers)
__device__ float4 g_tr[MAXN * 16];   // A @ Wr^T + b
__device__ float4 g_h[MAXN * 16];    // hidden activations
__device__ int    g_deg[MAXN];
__device__ int    g_bkt[MAXN * CAP]; // fixed-capacity incoming-neighbor buckets
__device__ int    g_is64;

// ---------------- packed f32x2 helpers ----------------

__device__ __forceinline__ unsigned long long dup2(float w) {
    unsigned long long r;
    asm("mov.b64 %0, {%1, %1};" : "=l"(r) : "f"(w));
    return r;
}
__device__ __forceinline__ void ffma2(unsigned long long& d,
                                      unsigned long long a, unsigned long long b) {
    asm("fma.rn.f32x2 %0, %1, %2, %0;" : "+l"(d) : "l"(a), "l"(b));
}

// ---------------- init: zero degrees + edge dtype detection ----------------

__global__ void k_init(const int* __restrict__ w, int n) {
    int i = blockIdx.x * blockDim.x + threadIdx.x;
    if (i < n) g_deg[i] = 0;
    if (blockIdx.x == 0) {
        __shared__ int nonzero;
        if (threadIdx.x == 0) nonzero = 0;
        __syncthreads();
        if (threadIdx.x < 128 && w[2 * threadIdx.x + 1] != 0) atomicOr(&nonzero, 1);
        __syncthreads();
        if (threadIdx.x == 0) g_is64 = (nonzero == 0) ? 1 : 0;
    }
}

// ---------------- fused dual-GEMM tile (single k-loop, swizzled smem) --------
// Tl[r0..r0+63] = A@Wl^T ; Tr = A@Wr^T + b. 128 threads.
// As[64][64]:  (k,row) at col row ^ 2*(k>>2)           (conflict-free both ways)
// Wb[64][128]: logical col 2j=Wl[j][k], 2j+1=Wr[j][k],
//              stored at col (2j) ^ 4*((k>>2)&7)        (LDS.128-aligned reads)
// Thread (tx=t&15, ty=t>>4) owns row-pairs {16p+2ty,16p+2ty+1} (p=0..3)
// x cols {4tx..4tx+3} for BOTH outputs.

__device__ __forceinline__ void gemm_tile(
        const float4* __restrict__ A,
        const float*  __restrict__ Wl, const float* __restrict__ Wr,
        const float*  __restrict__ bias, int n, int bid,
        float (*As)[64], float (*Wb)[128]) {
    int t  = threadIdx.x;
    int tx = t & 15;
    int ty = t >> 4;
    int r0 = bid * 64;

    // stage A transposed + swizzled
#pragma unroll
    for (int it = 0; it < 8; it++) {
        int f4  = it * 128 + t;
        int row = f4 >> 4, kq = f4 & 15;
        int rg  = r0 + row;
        float4 v = (rg < n) ? A[(size_t)rg * 16 + kq]
                            : make_float4(0.f, 0.f, 0.f, 0.f);
        int col = row ^ (2 * kq);           // sA(k)=2*(k>>2)=2*kq for k=4kq+c
        As[4 * kq + 0][col] = v.x;
        As[4 * kq + 1][col] = v.y;
        As[4 * kq + 2][col] = v.z;
        As[4 * kq + 3][col] = v.w;
    }
    // stage Wl/Wr interleaved + swizzled
#pragma unroll
    for (int it = 0; it < 8; it++) {
        int f4 = it * 128 + t;
        int j = f4 >> 4, kq = f4 & 15;
        float4 vl = ((const float4*)Wl)[j * 16 + kq];
        float4 vr = ((const float4*)Wr)[j * 16 + kq];
        int sW  = 4 * (kq & 7);
        int col = (2 * j) ^ sW;
        *(float2*)&Wb[4 * kq + 0][col] = make_float2(vl.x, vr.x);
        *(float2*)&Wb[4 * kq + 1][col] = make_float2(vl.y, vr.y);
        *(float2*)&Wb[4 * kq + 2][col] = make_float2(vl.z, vr.z);
        *(float2*)&Wb[4 * kq + 3][col] = make_float2(vl.w, vr.w);
    }
    __syncthreads();

    unsigned long long accL[4][4], accR[4][4];
#pragma unroll
    for (int p = 0; p < 4; p++)
#pragma unroll
        for (int c = 0; c < 4; c++) { accL[p][c] = 0ull; accR[p][c] = 0ull; }

    int colA0 = 2 * ty;
    int colW0 = 8 * tx;

#pragma unroll 8
    for (int k = 0; k < 64; k++) {
        int sA = 2 * (k >> 2);
        int sW = 4 * ((k >> 2) & 7);
        unsigned long long a2[4];
#pragma unroll
        for (int p = 0; p < 4; p++)
            a2[p] = *(const unsigned long long*)&As[k][(16 * p + colA0) ^ sA];
        float4 w0 = *(const float4*)&Wb[k][colW0 ^ sW];        // wl0,wr0,wl1,wr1
        float4 w1 = *(const float4*)&Wb[k][(colW0 + 4) ^ sW];  // wl2,wr2,wl3,wr3
        unsigned long long wl[4] = {dup2(w0.x), dup2(w0.z), dup2(w1.x), dup2(w1.z)};
        unsigned long long wr[4] = {dup2(w0.y), dup2(w0.w), dup2(w1.y), dup2(w1.w)};
#pragma unroll
        for (int p = 0; p < 4; p++) {
#pragma unroll
            for (int c = 0; c < 4; c++) {
                ffma2(accL[p][c], a2[p], wl[c]);
                ffma2(accR[p][c], a2[p], wr[c]);
            }
        }
    }

    float4 bj = *(const float4*)&bias[tx * 4];
#pragma unroll
    for (int p = 0; p < 4; p++) {
        int r = r0 + 16 * p + 2 * ty;
        float2 l0 = *(float2*)&accL[p][0];
        float2 l1 = *(float2*)&accL[p][1];
        float2 l2 = *(float2*)&accL[p][2];
        float2 l3 = *(float2*)&accL[p][3];
        float2 q0 = *(float2*)&accR[p][0];
        float2 q1 = *(float2*)&accR[p][1];
        float2 q2 = *(float2*)&accR[p][2];
        float2 q3 = *(float2*)&accR[p][3];
        if (r < n) {
            g_tl[(size_t)r * 16 + tx] = make_float4(l0.x, l1.x, l2.x, l3.x);
            g_tr[(size_t)r * 16 + tx] =
                make_float4(q0.x + bj.x, q1.x + bj.y, q2.x + bj.z, q3.x + bj.w);
        }
        if (r + 1 < n) {
            g_tl[(size_t)(r + 1) * 16 + tx] = make_float4(l0.y, l1.y, l2.y, l3.y);
            g_tr[(size_t)(r + 1) * 16 + tx] =
                make_float4(q0.y + bj.x, q1.y + bj.y, q2.y + bj.z, q3.y + bj.w);
        }
    }
}

// ---------------- kernel 2: layer-1 GEMM || bucket fill (disjoint blocks) ----

__global__ void __launch_bounds__(128, 4) k_gemm1_fill(
        const float4* __restrict__ x,
        const float*  __restrict__ Wl, const float* __restrict__ Wr,
        const float*  __restrict__ bias,
        const int* __restrict__ w, int E, int n, int gemm_blocks) {
    __shared__ __align__(16) float As[64][64];
    __shared__ __align__(16) float Wb[64][128];
    if ((int)blockIdx.x < gemm_blocks) {
        gemm_tile(x, Wl, Wr, bias, n, blockIdx.x, As, Wb);
    } else {
        int e = (blockIdx.x - gemm_blocks) * 128 + threadIdx.x;
        if (e < E) {
            int src, dst;
            if (g_is64) { src = w[2 * e]; dst = w[2 * (E + e)]; }
            else        { src = w[e];     dst = w[E + e]; }
            if (src >= 0 && src < n && dst >= 0 && dst < n) {
                int p = atomicAdd(&g_deg[dst], 1);
                if (p < CAP) g_bkt[dst * CAP + p] = src;
            }
        }
    }
}

// ---------------- kernel 4: layer-2 GEMM (A = g_h) ----------------

__global__ void __launch_bounds__(128, 4) k_gemm2(
        const float* __restrict__ Wl, const float* __restrict__ Wr,
        const float* __restrict__ bias, int n) {
    __shared__ __align__(16) float As[64][64];
    __shared__ __align__(16) float Wb[64][128];
    gemm_tile(g_h, Wl, Wr, bias, n, blockIdx.x, As, Wb);
}

// ---------------- aggregate + epilogue ----------------
// dst[g] = relu?( mean_{nbrs}(g_tl[nbr]) + g_tr[g] ).  16 lanes/node, float4.

template <bool RELU>
__global__ void k_agg(float4* __restrict__ outp, int n) {
    int g = (blockIdx.x * blockDim.x + threadIdx.x) >> 4;
    int l = threadIdx.x & 15;
    if (g >= n) return;
    int d  = g_deg[g];
    int dd = d < CAP ? d : CAP;
    const int* bp = &g_bkt[g * CAP];
    float4 acc = make_float4(0.f, 0.f, 0.f, 0.f);
    int j = 0;
    for (; j + 4 <= dd; j += 4) {
        int s0 = bp[j], s1 = bp[j + 1], s2 = bp[j + 2], s3 = bp[j + 3];
        float4 v0 = g_tl[(size_t)s0 * 16 + l];
        float4 v1 = g_tl[(size_t)s1 * 16 + l];
        float4 v2 = g_tl[(size_t)s2 * 16 + l];
        float4 v3 = g_tl[(size_t)s3 * 16 + l];
        acc.x += v0.x + v1.x + v2.x + v3.x;
        acc.y += v0.y + v1.y + v2.y + v3.y;
        acc.z += v0.z + v1.z + v2.z + v3.z;
        acc.w += v0.w + v1.w + v2.w + v3.w;
    }
    for (; j < dd; j++) {
        float4 v0 = g_tl[(size_t)bp[j] * 16 + l];
        acc.x += v0.x; acc.y += v0.y; acc.z += v0.z; acc.w += v0.w;
    }
    float inv = (d > 0) ? 1.f / (float)d : 0.f;
    float4 r = g_tr[(size_t)g * 16 + l];
    float4 v = make_float4(acc.x * inv + r.x, acc.y * inv + r.y,
                           acc.z * inv + r.z, acc.w * inv + r.w);
    if (RELU) {
        v.x = fmaxf(v.x, 0.f); v.y = fmaxf(v.y, 0.f);
        v.z = fmaxf(v.z, 0.f); v.w = fmaxf(v.w, 0.f);
    }
    float4* dst = outp ? outp : g_h;
    dst[(size_t)g * 16 + l] = v;
}

extern "C" void kernel_launch(void* const* d_in, const int* in_sizes, int n_in,
                              void* d_out, int out_size) {
    const float* x   = (const float*)d_in[0];
    const int*   ei  = (const int*)d_in[1];   // int32 words; may hold int64 data
    const float* Wl1 = (const float*)d_in[2];
    const float* Wr1 = (const float*)d_in[3];
    const float* b1  = (const float*)d_in[4];
    const float* Wl2 = (const float*)d_in[5];
    const float* Wr2 = (const float*)d_in[6];
    const float* b2  = (const float*)d_in[7];
    float* out = (float*)d_out;

    int n = in_sizes[0] / DD;
    int E = in_sizes[1] / 2;

    int gemm_blocks = (n + 63) / 64;
    int fill_blocks = (E + 127) / 128;
    int agg_blocks  = (n * 16 + 255) / 256;

    // 1) zero degrees + detect edge dtype
    k_init<<<(n + 255) / 256, 256>>>(ei, n);
    // 2) layer-1 fused dual GEMM concurrent with bucket fill
    k_gemm1_fill<<<gemm_blocks + fill_blocks, 128>>>(
        (const float4*)x, Wl1, Wr1, b1, ei, E, n, gemm_blocks);
    // 3) h = relu(mean(Tl) + Tr)
    k_agg<true><<<agg_blocks, 256>>>(nullptr, n);
    // 4) layer-2 fused dual GEMM
    k_gemm2<<<gemm_blocks, 128>>>(Wl2, Wr2, b2, n);
    // 5) out = mean(Tl) + Tr
    k_agg<false><<<agg_blocks, 256>>>((float4*)out, n);
}